// round 1
// baseline (speedup 1.0000x reference)
#include <cuda_runtime.h>
#include <math.h>

#define B_ 8
#define N_ 16384
#define M_ 512
#define K_ 32
#define C_ 6
#define TOKD_ 384

// -------------------- scratch (no allocations allowed) --------------------
__device__ int    g_center_idx[B_ * M_];
__device__ float  g_centers[B_ * M_ * 3];
__device__ int    g_gidx[B_ * M_ * K_];
__device__ float4 g_xyz[B_ * N_];   // x,y,z,|p|^2 packed for coalesced loads

// -------------------- helpers --------------------
__device__ __forceinline__ unsigned okey(float f) {
    // order-preserving transform for float -> unsigned
    unsigned u = __float_as_uint(f);
    unsigned mask = (u & 0x80000000u) ? 0xFFFFFFFFu : 0x80000000u;
    return u ^ mask;
}

// -------------------- pack xyz --------------------
__global__ void pack_kernel(const float* __restrict__ pts) {
    int i = blockIdx.x * blockDim.x + threadIdx.x;
    if (i < B_ * N_) {
        const float* p = pts + (size_t)i * C_;
        float x = p[0], y = p[1], z = p[2];
        g_xyz[i] = make_float4(x, y, z, x * x + y * y + z * z);
    }
}

// -------------------- farthest point sampling --------------------
// 1 block per batch, 1024 threads. xyz SoA in SMEM, dist in registers.
// Matches jnp.argmax semantics: ties -> lowest index.
__global__ void __launch_bounds__(1024, 1) fps_kernel(float* centers_out) {
    extern __shared__ float fsm[];
    float* sx = fsm;
    float* sy = fsm + N_;
    float* sz = fsm + 2 * N_;
    float* rd = fsm + 3 * N_;          // 32 floats
    int*   ri = (int*)(rd + 32);       // 32 ints
    int*   sfar = ri + 32;             // 1 int

    const int b = blockIdx.x;
    const int tid = threadIdx.x;
    const int lane = tid & 31, wid = tid >> 5;

    for (int n = tid; n < N_; n += 1024) {
        float4 q = g_xyz[b * N_ + n];
        sx[n] = q.x; sy[n] = q.y; sz[n] = q.z;
    }
    float dist[16];
#pragma unroll
    for (int i = 0; i < 16; i++) dist[i] = 1e10f;   // BIG, same f32 rounding as ref
    __syncthreads();

    int far = 0;
    for (int it = 0; it < M_; ++it) {
        float cx = sx[far], cy = sy[far], cz = sz[far];
        if (tid == 0) {
            g_center_idx[b * M_ + it] = far;
            float* gc = g_centers + (size_t)(b * M_ + it) * 3;
            gc[0] = cx; gc[1] = cy; gc[2] = cz;
            if (centers_out) {
                float* oc = centers_out + (size_t)(b * M_ + it) * 3;
                oc[0] = cx; oc[1] = cy; oc[2] = cz;
            }
        }
        float bd = -1.0f; int bi = 0x7fffffff;
#pragma unroll
        for (int i = 0; i < 16; i++) {
            int n = i * 1024 + tid;
            float dx = sx[n] - cx, dy = sy[n] - cy, dz = sz[n] - cz;
            float d = dx * dx + dy * dy + dz * dz;
            float nd = fminf(dist[i], d);
            dist[i] = nd;
            if (nd > bd) { bd = nd; bi = n; }   // strict >, n ascending -> first max
        }
#pragma unroll
        for (int off = 16; off; off >>= 1) {
            float od = __shfl_down_sync(0xffffffffu, bd, off);
            int   oi = __shfl_down_sync(0xffffffffu, bi, off);
            if (od > bd || (od == bd && oi < bi)) { bd = od; bi = oi; }
        }
        if (lane == 0) { rd[wid] = bd; ri[wid] = bi; }
        __syncthreads();
        if (wid == 0) {
            float vb = rd[lane]; int vi = ri[lane];
#pragma unroll
            for (int off = 16; off; off >>= 1) {
                float od = __shfl_down_sync(0xffffffffu, vb, off);
                int   oi = __shfl_down_sync(0xffffffffu, vi, off);
                if (od > vb || (od == vb && oi < vi)) { vb = od; vi = oi; }
            }
            if (lane == 0) *sfar = vi;
        }
        __syncthreads();
        far = *sfar;
    }
}

// -------------------- kNN (k=32 smallest d2, exact radix select) --------------------
// 1 block per (b, m) center. d2 in SMEM, 3-level radix select on ordered keys.
// Ties at the boundary: lowest index first (matches lax.top_k).
__global__ void __launch_bounds__(256) knn_kernel() {
    extern __shared__ float ksm[];
    float* d2s   = ksm;                      // N_
    int*   hist  = (int*)(ksm + N_);         // 2048
    int*   scansm = hist + 2048;             // 256
    int*   eql   = scansm + 256;             // 64
    int*   ctrs  = eql + 64;                 // [less, eq, sel_digit, sel_kk]

    const int bid = blockIdx.x;
    const int b = bid >> 9;
    const int tid = threadIdx.x;

    float cx = g_centers[bid * 3 + 0];
    float cy = g_centers[bid * 3 + 1];
    float cz = g_centers[bid * 3 + 2];
    float cc2 = cx * cx + cy * cy + cz * cz;

    for (int n = tid; n < N_; n += 256) {
        float4 q = g_xyz[b * N_ + n];
        float dot = cx * q.x + cy * q.y + cz * q.z;
        d2s[n] = cc2 - 2.0f * dot + q.w;     // same formula as reference
    }
    __syncthreads();

    unsigned prefix = 0u, pmask = 0u;
    int kk = K_;
    for (int lvl = 0; lvl < 3; ++lvl) {
        const int sh = (lvl == 0) ? 21 : ((lvl == 1) ? 10 : 0);
        const int nb = (lvl == 2) ? 1024 : 2048;
        for (int i = tid; i < 2048; i += 256) hist[i] = 0;
        __syncthreads();
        for (int n = tid; n < N_; n += 256) {
            unsigned u = okey(d2s[n]);
            if ((u & pmask) == prefix)
                atomicAdd(&hist[(u >> sh) & (unsigned)(nb - 1)], 1);
        }
        __syncthreads();
        const int per = nb / 256;
        int s = 0;
        for (int t = 0; t < per; ++t) s += hist[tid * per + t];
        scansm[tid] = s;
        __syncthreads();
        for (int off = 1; off < 256; off <<= 1) {
            int v = (tid >= off) ? scansm[tid - off] : 0;
            __syncthreads();
            scansm[tid] += v;
            __syncthreads();
        }
        int excl = scansm[tid] - s;
        if (excl < kk && excl + s >= kk) {
            int cum = excl;
            for (int t = 0; t < per; ++t) {
                int c = hist[tid * per + t];
                if (cum + c >= kk) { ctrs[2] = tid * per + t; ctrs[3] = kk - cum; break; }
                cum += c;
            }
        }
        __syncthreads();
        prefix |= ((unsigned)ctrs[2]) << sh;
        pmask  |= ((unsigned)(nb - 1)) << sh;
        kk = ctrs[3];
        __syncthreads();
    }
    // prefix == ordered key of the 32nd smallest d2 (exact)
    if (tid == 0) { ctrs[0] = 0; ctrs[1] = 0; }
    __syncthreads();
    int* gout = g_gidx + (size_t)bid * K_;
    for (int n = tid; n < N_; n += 256) {
        unsigned u = okey(d2s[n]);
        if (u < prefix) {
            int p = atomicAdd(&ctrs[0], 1);
            gout[p] = n;
        } else if (u == prefix) {
            int e = atomicAdd(&ctrs[1], 1);
            if (e < 64) eql[e] = n;
        }
    }
    __syncthreads();
    if (tid == 0) {
        int less = ctrs[0];
        int eq = ctrs[1];
        int need = K_ - less;
        if (eq <= 64) {
            for (int s2 = 0; s2 < need; ++s2) {     // pick `need` smallest indices
                int mb = 0x7fffffff, mi = 0;
                for (int t = 0; t < eq; ++t)
                    if (eql[t] < mb) { mb = eql[t]; mi = t; }
                gout[less + s2] = mb;
                eql[mi] = 0x7fffffff;
            }
        } else {   // pathological duplicate case: ordered rescan
            int c = 0;
            for (int n = 0; n < N_ && c < need; ++n)
                if (okey(d2s[n]) == prefix) { gout[less + c] = n; ++c; }
        }
    }
}

// -------------------- fused encoder MLP + maxpool --------------------
template<int CIN, int DOUT>
__device__ __forceinline__ void enc_layer(
    const float* __restrict__ in, float* __restrict__ out,
    const float* __restrict__ w, const float* __restrict__ bias,
    const float* __restrict__ gg, const float* __restrict__ bb,
    const float* __restrict__ mm, const float* __restrict__ vv,
    int warp, int lane)
{
    constexpr int JT = DOUT / 32;
    float acc[4][JT];
#pragma unroll
    for (int r = 0; r < 4; r++)
#pragma unroll
        for (int j = 0; j < JT; j++) acc[r][j] = 0.f;
    const int r0 = warp * 4;
    const float* in0 = in + (r0 + 0) * CIN;
    const float* in1 = in + (r0 + 1) * CIN;
    const float* in2 = in + (r0 + 2) * CIN;
    const float* in3 = in + (r0 + 3) * CIN;
#pragma unroll 4
    for (int c = 0; c < CIN; ++c) {
        float a0 = in0[c], a1 = in1[c], a2 = in2[c], a3 = in3[c];
        const float* wr = w + (size_t)c * DOUT + lane;
#pragma unroll
        for (int jj = 0; jj < JT; ++jj) {
            float wv = __ldg(wr + jj * 32);
            acc[0][jj] = fmaf(a0, wv, acc[0][jj]);
            acc[1][jj] = fmaf(a1, wv, acc[1][jj]);
            acc[2][jj] = fmaf(a2, wv, acc[2][jj]);
            acc[3][jj] = fmaf(a3, wv, acc[3][jj]);
        }
    }
#pragma unroll
    for (int jj = 0; jj < JT; ++jj) {
        int j = lane + jj * 32;
        float bj = __ldg(bias + j);
        float sc = __ldg(gg + j) * rsqrtf(__ldg(vv + j) + 1e-5f);
        float mj = __ldg(mm + j);
        float betaj = __ldg(bb + j);
#pragma unroll
        for (int rr = 0; rr < 4; ++rr) {
            float y = acc[rr][jj] + bj;
            float v = (y - mj) * sc + betaj;
            out[(r0 + rr) * DOUT + j] = fmaxf(v, 0.0f);
        }
    }
}

__global__ void __launch_bounds__(256) encoder_kernel(
    const float* __restrict__ pts,
    const float* __restrict__ w1, const float* __restrict__ b1,
    const float* __restrict__ g1, const float* __restrict__ be1,
    const float* __restrict__ m1, const float* __restrict__ v1,
    const float* __restrict__ w2, const float* __restrict__ b2,
    const float* __restrict__ g2, const float* __restrict__ be2,
    const float* __restrict__ m2, const float* __restrict__ v2,
    const float* __restrict__ w3, const float* __restrict__ b3,
    const float* __restrict__ g3, const float* __restrict__ be3,
    const float* __restrict__ m3, const float* __restrict__ v3,
    const float* __restrict__ w4, const float* __restrict__ b4,
    float* __restrict__ tokens)
{
    extern __shared__ float esm[];
    float* bufA = esm;                 // 32*128
    float* bufB = esm + 32 * 128;      // 32*256
    float* maxb = bufB + 32 * 256;     // 8*384

    const int gid = blockIdx.x;
    const int b = gid >> 9;
    const int tid = threadIdx.x;
    const int warp = tid >> 5, lane = tid & 31;

    if (tid < 32) {
        int n = g_gidx[(size_t)gid * K_ + tid];
        const float* p = pts + (size_t)(b * N_ + n) * C_;
        float cx = g_centers[gid * 3 + 0];
        float cy = g_centers[gid * 3 + 1];
        float cz = g_centers[gid * 3 + 2];
        float x = p[0], y = p[1], z = p[2];
        float* xr = bufA + tid * 9;
        xr[0] = x - cx; xr[1] = y - cy; xr[2] = z - cz;
        xr[3] = x; xr[4] = y; xr[5] = z;
        xr[6] = p[3]; xr[7] = p[4]; xr[8] = p[5];
    }
    __syncthreads();
    enc_layer<9, 64>(bufA, bufB, w1, b1, g1, be1, m1, v1, warp, lane);
    __syncthreads();
    enc_layer<64, 128>(bufB, bufA, w2, b2, g2, be2, m2, v2, warp, lane);
    __syncthreads();
    enc_layer<128, 256>(bufA, bufB, w3, b3, g3, be3, m3, v3, warp, lane);
    __syncthreads();
    // layer 4: 256 -> 384, bias only, max over the 32 rows
    {
        constexpr int JT = 12;
        float acc[4][JT];
#pragma unroll
        for (int r = 0; r < 4; r++)
#pragma unroll
            for (int j = 0; j < JT; j++) acc[r][j] = 0.f;
        const int r0 = warp * 4;
        const float* in0 = bufB + (r0 + 0) * 256;
        const float* in1 = bufB + (r0 + 1) * 256;
        const float* in2 = bufB + (r0 + 2) * 256;
        const float* in3 = bufB + (r0 + 3) * 256;
#pragma unroll 4
        for (int c = 0; c < 256; ++c) {
            float a0 = in0[c], a1 = in1[c], a2 = in2[c], a3 = in3[c];
            const float* wr = w4 + (size_t)c * 384 + lane;
#pragma unroll
            for (int jj = 0; jj < JT; ++jj) {
                float wv = __ldg(wr + jj * 32);
                acc[0][jj] = fmaf(a0, wv, acc[0][jj]);
                acc[1][jj] = fmaf(a1, wv, acc[1][jj]);
                acc[2][jj] = fmaf(a2, wv, acc[2][jj]);
                acc[3][jj] = fmaf(a3, wv, acc[3][jj]);
            }
        }
#pragma unroll
        for (int jj = 0; jj < JT; ++jj) {
            int j = lane + jj * 32;
            float bj = __ldg(b4 + j);
            float mx = fmaxf(fmaxf(acc[0][jj], acc[1][jj]),
                             fmaxf(acc[2][jj], acc[3][jj])) + bj;
            maxb[warp * 384 + j] = mx;
        }
        __syncthreads();
        for (int j = tid; j < 384; j += 256) {
            float mx = maxb[j];
#pragma unroll
            for (int w = 1; w < 8; ++w) mx = fmaxf(mx, maxb[w * 384 + j]);
            tokens[(size_t)gid * 384 + j] = mx;
        }
    }
}

// -------------------- positional MLP (exact gelu) --------------------
__global__ void __launch_bounds__(128) pos_kernel(
    const float* __restrict__ pw1, const float* __restrict__ pb1,
    const float* __restrict__ pw2, const float* __restrict__ pb2,
    float* __restrict__ tokens)
{
    __shared__ float h[128];
    const int gid = blockIdx.x;
    const int tid = threadIdx.x;
    float cx = g_centers[gid * 3 + 0];
    float cy = g_centers[gid * 3 + 1];
    float cz = g_centers[gid * 3 + 2];
    float t = cx * __ldg(pw1 + tid) + cy * __ldg(pw1 + 128 + tid)
            + cz * __ldg(pw1 + 256 + tid) + __ldg(pb1 + tid);
    float ge = 0.5f * t * (1.0f + erff(t * 0.70710678118654752f));
    h[tid] = ge;
    __syncthreads();
#pragma unroll
    for (int jj = 0; jj < 3; ++jj) {
        int col = tid + jj * 128;
        float acc = __ldg(pb2 + col);
#pragma unroll 4
        for (int c = 0; c < 128; ++c)
            acc = fmaf(h[c], __ldg(pw2 + (size_t)c * 384 + col), acc);
        tokens[(size_t)gid * 384 + col] += acc;
    }
}

// -------------------- launch --------------------
extern "C" void kernel_launch(void* const* d_in, const int* in_sizes, int n_in,
                              void* d_out, int out_size)
{
    const float* pts = (const float*)d_in[0];
    const float* w1 = (const float*)d_in[1],  *b1 = (const float*)d_in[2];
    const float* g1 = (const float*)d_in[3],  *be1 = (const float*)d_in[4];
    const float* m1 = (const float*)d_in[5],  *v1 = (const float*)d_in[6];
    const float* w2 = (const float*)d_in[7],  *b2 = (const float*)d_in[8];
    const float* g2 = (const float*)d_in[9],  *be2 = (const float*)d_in[10];
    const float* m2 = (const float*)d_in[11], *v2 = (const float*)d_in[12];
    const float* w3 = (const float*)d_in[13], *b3 = (const float*)d_in[14];
    const float* g3 = (const float*)d_in[15], *be3 = (const float*)d_in[16];
    const float* m3 = (const float*)d_in[17], *v3 = (const float*)d_in[18];
    const float* w4 = (const float*)d_in[19], *b4 = (const float*)d_in[20];
    const float* pw1 = (const float*)d_in[21], *pb1 = (const float*)d_in[22];
    const float* pw2 = (const float*)d_in[23], *pb2 = (const float*)d_in[24];

    float* out = (float*)d_out;
    float* tokens = out;
    float* centers_out =
        (out_size >= B_ * M_ * TOKD_ + B_ * M_ * 3) ? (out + (size_t)B_ * M_ * TOKD_)
                                                    : nullptr;

    const int FPS_SMEM = (3 * N_ + 32 + 32 + 1) * 4;            // ~196.9 KB
    const int KNN_SMEM = (N_ + 2048 + 256 + 64 + 8) * 4;        // ~75 KB
    const int ENC_SMEM = (32 * 128 + 32 * 256 + 8 * 384) * 4;   // 61440 B

    cudaFuncSetAttribute(fps_kernel, cudaFuncAttributeMaxDynamicSharedMemorySize, FPS_SMEM);
    cudaFuncSetAttribute(knn_kernel, cudaFuncAttributeMaxDynamicSharedMemorySize, KNN_SMEM);
    cudaFuncSetAttribute(encoder_kernel, cudaFuncAttributeMaxDynamicSharedMemorySize, ENC_SMEM);

    pack_kernel<<<(B_ * N_ + 255) / 256, 256>>>(pts);
    fps_kernel<<<B_, 1024, FPS_SMEM>>>(centers_out);
    knn_kernel<<<B_ * M_, 256, KNN_SMEM>>>();
    encoder_kernel<<<B_ * M_, 256, ENC_SMEM>>>(
        pts, w1, b1, g1, be1, m1, v1, w2, b2, g2, be2, m2, v2,
        w3, b3, g3, be3, m3, v3, w4, b4, tokens);
    pos_kernel<<<B_ * M_, 128>>>(pw1, pb1, pw2, pb2, tokens);
}

// round 2
// speedup vs baseline: 1.0956x; 1.0956x over previous
#include <cuda_runtime.h>
#include <math.h>

#define B_ 8
#define N_ 16384
#define M_ 512
#define K_ 32
#define C_ 6
#define TOKD_ 384

// -------------------- scratch (no allocations allowed) --------------------
__device__ int    g_center_idx[B_ * M_];
__device__ float  g_centers[B_ * M_ * 3];
__device__ int    g_gidx[B_ * M_ * K_];
__device__ float4 g_xyz[B_ * N_];   // x,y,z,|p|^2 packed for coalesced loads

// -------------------- helpers --------------------
__device__ __forceinline__ unsigned okey(float f) {
    unsigned u = __float_as_uint(f);
    unsigned mask = (u & 0x80000000u) ? 0xFFFFFFFFu : 0x80000000u;
    return u ^ mask;
}

// packed f32x2 fma: d = a*b + c (elementwise, exact fp32)
__device__ __forceinline__ unsigned long long ffma2(
    unsigned long long a, unsigned long long b, unsigned long long c) {
    unsigned long long d;
    asm("fma.rn.f32x2 %0, %1, %2, %3;" : "=l"(d) : "l"(a), "l"(b), "l"(c));
    return d;
}
__device__ __forceinline__ unsigned long long dupf(float x) {
    unsigned long long d;
    asm("mov.b64 %0, {%1, %1};" : "=l"(d) : "f"(x));
    return d;
}
__device__ __forceinline__ unsigned long long pack2(float lo, float hi) {
    unsigned long long d;
    asm("mov.b64 %0, {%1, %2};" : "=l"(d) : "f"(lo), "f"(hi));
    return d;
}
__device__ __forceinline__ float2 unpk(unsigned long long v) {
    float lo, hi;
    asm("mov.b64 {%0, %1}, %2;" : "=f"(lo), "=f"(hi) : "l"(v));
    return make_float2(lo, hi);
}

// -------------------- pack xyz --------------------
__global__ void pack_kernel(const float* __restrict__ pts) {
    int i = blockIdx.x * blockDim.x + threadIdx.x;
    if (i < B_ * N_) {
        const float* p = pts + (size_t)i * C_;
        float x = p[0], y = p[1], z = p[2];
        g_xyz[i] = make_float4(x, y, z, x * x + y * y + z * z);
    }
}

// -------------------- farthest point sampling --------------------
__global__ void __launch_bounds__(1024, 1) fps_kernel(float* centers_out) {
    extern __shared__ float fsm[];
    float* sx = fsm;
    float* sy = fsm + N_;
    float* sz = fsm + 2 * N_;
    float* rd = fsm + 3 * N_;          // 32 floats
    int*   ri = (int*)(rd + 32);       // 32 ints
    int*   sfar = ri + 32;             // 1 int

    const int b = blockIdx.x;
    const int tid = threadIdx.x;
    const int lane = tid & 31, wid = tid >> 5;

    for (int n = tid; n < N_; n += 1024) {
        float4 q = g_xyz[b * N_ + n];
        sx[n] = q.x; sy[n] = q.y; sz[n] = q.z;
    }
    float dist[16];
#pragma unroll
    for (int i = 0; i < 16; i++) dist[i] = 1e10f;
    __syncthreads();

    int far = 0;
    for (int it = 0; it < M_; ++it) {
        float cx = sx[far], cy = sy[far], cz = sz[far];
        if (tid == 0) {
            g_center_idx[b * M_ + it] = far;
            float* gc = g_centers + (size_t)(b * M_ + it) * 3;
            gc[0] = cx; gc[1] = cy; gc[2] = cz;
            if (centers_out) {
                float* oc = centers_out + (size_t)(b * M_ + it) * 3;
                oc[0] = cx; oc[1] = cy; oc[2] = cz;
            }
        }
        float bd = -1.0f; int bi = 0x7fffffff;
#pragma unroll
        for (int i = 0; i < 16; i++) {
            int n = i * 1024 + tid;
            float dx = sx[n] - cx, dy = sy[n] - cy, dz = sz[n] - cz;
            float d = dx * dx + dy * dy + dz * dz;
            float nd = fminf(dist[i], d);
            dist[i] = nd;
            if (nd > bd) { bd = nd; bi = n; }
        }
#pragma unroll
        for (int off = 16; off; off >>= 1) {
            float od = __shfl_down_sync(0xffffffffu, bd, off);
            int   oi = __shfl_down_sync(0xffffffffu, bi, off);
            if (od > bd || (od == bd && oi < bi)) { bd = od; bi = oi; }
        }
        if (lane == 0) { rd[wid] = bd; ri[wid] = bi; }
        __syncthreads();
        if (wid == 0) {
            float vb = rd[lane]; int vi = ri[lane];
#pragma unroll
            for (int off = 16; off; off >>= 1) {
                float od = __shfl_down_sync(0xffffffffu, vb, off);
                int   oi = __shfl_down_sync(0xffffffffu, vi, off);
                if (od > vb || (od == vb && oi < vi)) { vb = od; vi = oi; }
            }
            if (lane == 0) *sfar = vi;
        }
        __syncthreads();
        far = *sfar;
    }
}

// -------------------- kNN (exact radix select, lowest-index ties) --------------------
__global__ void __launch_bounds__(256) knn_kernel() {
    extern __shared__ float ksm[];
    float* d2s   = ksm;                      // N_
    int*   hist  = (int*)(ksm + N_);         // 2048
    int*   scansm = hist + 2048;             // 256
    int*   eql   = scansm + 256;             // 64
    int*   ctrs  = eql + 64;                 // [less, eq, sel_digit, sel_kk]

    const int bid = blockIdx.x;
    const int b = bid >> 9;
    const int tid = threadIdx.x;

    float cx = g_centers[bid * 3 + 0];
    float cy = g_centers[bid * 3 + 1];
    float cz = g_centers[bid * 3 + 2];
    float cc2 = cx * cx + cy * cy + cz * cz;

    for (int n = tid; n < N_; n += 256) {
        float4 q = g_xyz[b * N_ + n];
        float dot = cx * q.x + cy * q.y + cz * q.z;
        d2s[n] = cc2 - 2.0f * dot + q.w;
    }
    __syncthreads();

    unsigned prefix = 0u, pmask = 0u;
    int kk = K_;
    for (int lvl = 0; lvl < 3; ++lvl) {
        const int sh = (lvl == 0) ? 21 : ((lvl == 1) ? 10 : 0);
        const int nb = (lvl == 2) ? 1024 : 2048;
        for (int i = tid; i < 2048; i += 256) hist[i] = 0;
        __syncthreads();
        for (int n = tid; n < N_; n += 256) {
            unsigned u = okey(d2s[n]);
            if ((u & pmask) == prefix)
                atomicAdd(&hist[(u >> sh) & (unsigned)(nb - 1)], 1);
        }
        __syncthreads();
        const int per = nb / 256;
        int s = 0;
        for (int t = 0; t < per; ++t) s += hist[tid * per + t];
        scansm[tid] = s;
        __syncthreads();
        for (int off = 1; off < 256; off <<= 1) {
            int v = (tid >= off) ? scansm[tid - off] : 0;
            __syncthreads();
            scansm[tid] += v;
            __syncthreads();
        }
        int excl = scansm[tid] - s;
        if (excl < kk && excl + s >= kk) {
            int cum = excl;
            for (int t = 0; t < per; ++t) {
                int c = hist[tid * per + t];
                if (cum + c >= kk) { ctrs[2] = tid * per + t; ctrs[3] = kk - cum; break; }
                cum += c;
            }
        }
        __syncthreads();
        prefix |= ((unsigned)ctrs[2]) << sh;
        pmask  |= ((unsigned)(nb - 1)) << sh;
        kk = ctrs[3];
        __syncthreads();
    }
    if (tid == 0) { ctrs[0] = 0; ctrs[1] = 0; }
    __syncthreads();
    int* gout = g_gidx + (size_t)bid * K_;
    for (int n = tid; n < N_; n += 256) {
        unsigned u = okey(d2s[n]);
        if (u < prefix) {
            int p = atomicAdd(&ctrs[0], 1);
            gout[p] = n;
        } else if (u == prefix) {
            int e = atomicAdd(&ctrs[1], 1);
            if (e < 64) eql[e] = n;
        }
    }
    __syncthreads();
    if (tid == 0) {
        int less = ctrs[0];
        int eq = ctrs[1];
        int need = K_ - less;
        if (eq <= 64) {
            for (int s2 = 0; s2 < need; ++s2) {
                int mb = 0x7fffffff, mi = 0;
                for (int t = 0; t < eq; ++t)
                    if (eql[t] < mb) { mb = eql[t]; mi = t; }
                gout[less + s2] = mb;
                eql[mi] = 0x7fffffff;
            }
        } else {
            int c = 0;
            for (int n = 0; n < N_ && c < need; ++n)
                if (okey(d2s[n]) == prefix) { gout[less + c] = n; ++c; }
        }
    }
}

// -------------------- fused encoder (f32x2 packed FMA) --------------------
// 128 threads/CTA. Warp w owns rows 8w..8w+7 as 4 row-pairs packed in f32x2.
// Activations live transposed in SMEM: act[c*34 + r] (stride 34: conflict-free,
// 8B-aligned row-pairs for broadcast LDS.64).
#define AST 34

template<int CIN, int DOUT, int JT>
__device__ __forceinline__ void enc_pass(
    const float* __restrict__ in, float* __restrict__ out,
    const float* __restrict__ w, int colbase,
    const float* __restrict__ bias,
    const float* __restrict__ gg, const float* __restrict__ bb,
    const float* __restrict__ mm, const float* __restrict__ vv,
    int warp, int lane)
{
    unsigned long long acc[4][JT];
#pragma unroll
    for (int p = 0; p < 4; p++)
#pragma unroll
        for (int j = 0; j < JT; j++) acc[p][j] = 0ull;
    const int rbase = warp * 8;
    const float* wptr = w + colbase + lane;
#pragma unroll 4
    for (int c = 0; c < CIN; ++c) {
        const float* inc = in + c * AST + rbase;
        unsigned long long a0 = *(const unsigned long long*)(inc + 0);
        unsigned long long a1 = *(const unsigned long long*)(inc + 2);
        unsigned long long a2 = *(const unsigned long long*)(inc + 4);
        unsigned long long a3 = *(const unsigned long long*)(inc + 6);
        unsigned long long wd[JT];
#pragma unroll
        for (int j = 0; j < JT; j++)
            wd[j] = dupf(__ldg(wptr + (size_t)c * DOUT + 32 * j));
#pragma unroll
        for (int j = 0; j < JT; j++) {
            acc[0][j] = ffma2(a0, wd[j], acc[0][j]);
            acc[1][j] = ffma2(a1, wd[j], acc[1][j]);
            acc[2][j] = ffma2(a2, wd[j], acc[2][j]);
            acc[3][j] = ffma2(a3, wd[j], acc[3][j]);
        }
    }
#pragma unroll
    for (int j = 0; j < JT; j++) {
        int col = colbase + lane + 32 * j;
        float bj  = __ldg(bias + col);
        float sc  = __ldg(gg + col) * rsqrtf(__ldg(vv + col) + 1e-5f);
        float mj  = __ldg(mm + col);
        float bet = __ldg(bb + col);
        float* op = out + col * AST + rbase;
#pragma unroll
        for (int p = 0; p < 4; p++) {
            float2 v = unpk(acc[p][j]);
            float lo = fmaxf((v.x + bj - mj) * sc + bet, 0.0f);
            float hi = fmaxf((v.y + bj - mj) * sc + bet, 0.0f);
            *(unsigned long long*)(op + 2 * p) = pack2(lo, hi);
        }
    }
}

template<int CIN, int JT>
__device__ __forceinline__ void enc_l4(
    const float* __restrict__ in, const float* __restrict__ w, int colbase,
    const float* __restrict__ bias, float* __restrict__ maxb,
    int warp, int lane)
{
    unsigned long long acc[4][JT];
#pragma unroll
    for (int p = 0; p < 4; p++)
#pragma unroll
        for (int j = 0; j < JT; j++) acc[p][j] = 0ull;
    const int rbase = warp * 8;
    const float* wptr = w + colbase + lane;
#pragma unroll 2
    for (int c = 0; c < CIN; ++c) {
        const float* inc = in + c * AST + rbase;
        unsigned long long a0 = *(const unsigned long long*)(inc + 0);
        unsigned long long a1 = *(const unsigned long long*)(inc + 2);
        unsigned long long a2 = *(const unsigned long long*)(inc + 4);
        unsigned long long a3 = *(const unsigned long long*)(inc + 6);
        unsigned long long wd[JT];
#pragma unroll
        for (int j = 0; j < JT; j++)
            wd[j] = dupf(__ldg(wptr + (size_t)c * 384 + 32 * j));
#pragma unroll
        for (int j = 0; j < JT; j++) {
            acc[0][j] = ffma2(a0, wd[j], acc[0][j]);
            acc[1][j] = ffma2(a1, wd[j], acc[1][j]);
            acc[2][j] = ffma2(a2, wd[j], acc[2][j]);
            acc[3][j] = ffma2(a3, wd[j], acc[3][j]);
        }
    }
#pragma unroll
    for (int j = 0; j < JT; j++) {
        int col = colbase + lane + 32 * j;
        float mx = -1e30f;
#pragma unroll
        for (int p = 0; p < 4; p++) {
            float2 v = unpk(acc[p][j]);
            mx = fmaxf(mx, fmaxf(v.x, v.y));
        }
        maxb[warp * 384 + col] = mx + __ldg(bias + col);
    }
}

__global__ void __launch_bounds__(128, 3) encoder_kernel(
    const float* __restrict__ pts,
    const float* __restrict__ w1, const float* __restrict__ b1,
    const float* __restrict__ g1, const float* __restrict__ be1,
    const float* __restrict__ m1, const float* __restrict__ v1,
    const float* __restrict__ w2, const float* __restrict__ b2,
    const float* __restrict__ g2, const float* __restrict__ be2,
    const float* __restrict__ m2, const float* __restrict__ v2,
    const float* __restrict__ w3, const float* __restrict__ b3,
    const float* __restrict__ g3, const float* __restrict__ be3,
    const float* __restrict__ m3, const float* __restrict__ v3,
    const float* __restrict__ w4, const float* __restrict__ b4,
    float* __restrict__ tokens)
{
    extern __shared__ float esm[];
    float* buf0 = esm;                       // 9*34   = 306
    float* bufA = esm + 306;                 // 256*34 = 8704
    float* bufB = esm + 306 + 8704;          // 128*34 = 4352
    float* maxb = esm + 306 + 8704 + 4352;   // 4*384  = 1536

    const int gid = blockIdx.x;
    const int b = gid >> 9;
    const int tid = threadIdx.x;
    const int warp = tid >> 5, lane = tid & 31;

    if (tid < 32) {
        int n = g_gidx[(size_t)gid * K_ + tid];
        const float* p = pts + (size_t)(b * N_ + n) * C_;
        float cx = g_centers[gid * 3 + 0];
        float cy = g_centers[gid * 3 + 1];
        float cz = g_centers[gid * 3 + 2];
        float x = p[0], y = p[1], z = p[2];
        buf0[0 * AST + tid] = x - cx;
        buf0[1 * AST + tid] = y - cy;
        buf0[2 * AST + tid] = z - cz;
        buf0[3 * AST + tid] = x;
        buf0[4 * AST + tid] = y;
        buf0[5 * AST + tid] = z;
        buf0[6 * AST + tid] = p[3];
        buf0[7 * AST + tid] = p[4];
        buf0[8 * AST + tid] = p[5];
    }
    __syncthreads();
    enc_pass<9, 64, 2>(buf0, bufA, w1, 0, b1, g1, be1, m1, v1, warp, lane);
    __syncthreads();
    enc_pass<64, 128, 4>(bufA, bufB, w2, 0, b2, g2, be2, m2, v2, warp, lane);
    __syncthreads();
    enc_pass<128, 256, 4>(bufB, bufA, w3, 0,   b3, g3, be3, m3, v3, warp, lane);
    enc_pass<128, 256, 4>(bufB, bufA, w3, 128, b3, g3, be3, m3, v3, warp, lane);
    __syncthreads();
    enc_l4<256, 6>(bufA, w4, 0,   b4, maxb, warp, lane);
    enc_l4<256, 6>(bufA, w4, 192, b4, maxb, warp, lane);
    __syncthreads();
    for (int col = tid; col < 384; col += 128) {
        float mx = maxb[col];
#pragma unroll
        for (int w = 1; w < 4; ++w) mx = fmaxf(mx, maxb[w * 384 + col]);
        tokens[(size_t)gid * 384 + col] = mx;
    }
}

// -------------------- positional MLP (exact gelu) --------------------
__global__ void __launch_bounds__(128) pos_kernel(
    const float* __restrict__ pw1, const float* __restrict__ pb1,
    const float* __restrict__ pw2, const float* __restrict__ pb2,
    float* __restrict__ tokens)
{
    __shared__ float h[128];
    const int gid = blockIdx.x;
    const int tid = threadIdx.x;
    float cx = g_centers[gid * 3 + 0];
    float cy = g_centers[gid * 3 + 1];
    float cz = g_centers[gid * 3 + 2];
    float t = cx * __ldg(pw1 + tid) + cy * __ldg(pw1 + 128 + tid)
            + cz * __ldg(pw1 + 256 + tid) + __ldg(pb1 + tid);
    float ge = 0.5f * t * (1.0f + erff(t * 0.70710678118654752f));
    h[tid] = ge;
    __syncthreads();
#pragma unroll
    for (int jj = 0; jj < 3; ++jj) {
        int col = tid + jj * 128;
        float acc = __ldg(pb2 + col);
#pragma unroll 4
        for (int c = 0; c < 128; ++c)
            acc = fmaf(h[c], __ldg(pw2 + (size_t)c * 384 + col), acc);
        tokens[(size_t)gid * 384 + col] += acc;
    }
}

// -------------------- launch --------------------
extern "C" void kernel_launch(void* const* d_in, const int* in_sizes, int n_in,
                              void* d_out, int out_size)
{
    const float* pts = (const float*)d_in[0];
    const float* w1 = (const float*)d_in[1],  *b1 = (const float*)d_in[2];
    const float* g1 = (const float*)d_in[3],  *be1 = (const float*)d_in[4];
    const float* m1 = (const float*)d_in[5],  *v1 = (const float*)d_in[6];
    const float* w2 = (const float*)d_in[7],  *b2 = (const float*)d_in[8];
    const float* g2 = (const float*)d_in[9],  *be2 = (const float*)d_in[10];
    const float* m2 = (const float*)d_in[11], *v2 = (const float*)d_in[12];
    const float* w3 = (const float*)d_in[13], *b3 = (const float*)d_in[14];
    const float* g3 = (const float*)d_in[15], *be3 = (const float*)d_in[16];
    const float* m3 = (const float*)d_in[17], *v3 = (const float*)d_in[18];
    const float* w4 = (const float*)d_in[19], *b4 = (const float*)d_in[20];
    const float* pw1 = (const float*)d_in[21], *pb1 = (const float*)d_in[22];
    const float* pw2 = (const float*)d_in[23], *pb2 = (const float*)d_in[24];

    float* out = (float*)d_out;
    float* tokens = out;
    float* centers_out =
        (out_size >= B_ * M_ * TOKD_ + B_ * M_ * 3) ? (out + (size_t)B_ * M_ * TOKD_)
                                                    : nullptr;

    const int FPS_SMEM = (3 * N_ + 32 + 32 + 1) * 4;
    const int KNN_SMEM = (N_ + 2048 + 256 + 64 + 8) * 4;
    const int ENC_SMEM = (306 + 8704 + 4352 + 1536) * 4;   // 59592 B

    cudaFuncSetAttribute(fps_kernel, cudaFuncAttributeMaxDynamicSharedMemorySize, FPS_SMEM);
    cudaFuncSetAttribute(knn_kernel, cudaFuncAttributeMaxDynamicSharedMemorySize, KNN_SMEM);
    cudaFuncSetAttribute(encoder_kernel, cudaFuncAttributeMaxDynamicSharedMemorySize, ENC_SMEM);

    pack_kernel<<<(B_ * N_ + 255) / 256, 256>>>(pts);
    fps_kernel<<<B_, 1024, FPS_SMEM>>>(centers_out);
    knn_kernel<<<B_ * M_, 256, KNN_SMEM>>>();
    encoder_kernel<<<B_ * M_, 128, ENC_SMEM>>>(
        pts, w1, b1, g1, be1, m1, v1, w2, b2, g2, be2, m2, v2,
        w3, b3, g3, be3, m3, v3, w4, b4, tokens);
    pos_kernel<<<B_ * M_, 128>>>(pw1, pb1, pw2, pb2, tokens);
}

// round 4
// speedup vs baseline: 1.1328x; 1.0339x over previous
#include <cuda_runtime.h>
#include <math.h>
#include <stdint.h>

#define B_ 8
#define N_ 16384
#define M_ 512
#define K_ 32
#define C_ 6
#define FPS_P 4096       // points per FPS CTA (N_/4)

// -------------------- scratch (no allocations allowed) --------------------
__device__ int    g_center_idx[B_ * M_];
__device__ float  g_centers[B_ * M_ * 3];
__device__ int    g_gidx[B_ * M_ * K_];
__device__ float4 g_xyz[B_ * N_];

// -------------------- helpers --------------------
__device__ __forceinline__ unsigned okey(float f) {
    unsigned u = __float_as_uint(f);
    unsigned mask = (u & 0x80000000u) ? 0xFFFFFFFFu : 0x80000000u;
    return u ^ mask;
}
__device__ __forceinline__ unsigned long long ffma2(
    unsigned long long a, unsigned long long b, unsigned long long c) {
    unsigned long long d;
    asm("fma.rn.f32x2 %0, %1, %2, %3;" : "=l"(d) : "l"(a), "l"(b), "l"(c));
    return d;
}
__device__ __forceinline__ unsigned long long dupf(float x) {
    unsigned long long d;
    asm("mov.b64 %0, {%1, %1};" : "=l"(d) : "f"(x));
    return d;
}
__device__ __forceinline__ unsigned long long pack2(float lo, float hi) {
    unsigned long long d;
    asm("mov.b64 %0, {%1, %2};" : "=l"(d) : "f"(lo), "f"(hi));
    return d;
}
__device__ __forceinline__ float2 unpk(unsigned long long v) {
    float lo, hi;
    asm("mov.b64 {%0, %1}, %2;" : "=f"(lo), "=f"(hi) : "l"(v));
    return make_float2(lo, hi);
}
__device__ __forceinline__ uint32_t smem_u32(const void* p) {
    uint32_t a;
    asm("{ .reg .u64 t; cvta.to.shared.u64 t, %1; cvt.u32.u64 %0, t; }" : "=r"(a) : "l"(p));
    return a;
}
__device__ __forceinline__ uint32_t mapa_sh(uint32_t addr, uint32_t rank) {
    uint32_t r;
    asm("mapa.shared::cluster.u32 %0, %1, %2;" : "=r"(r) : "r"(addr), "r"(rank));
    return r;
}
__device__ __forceinline__ void stsc_f(uint32_t a, float v) {
    asm volatile("st.shared::cluster.f32 [%0], %1;" :: "r"(a), "f"(v) : "memory");
}
__device__ __forceinline__ void stsc_i(uint32_t a, int v) {
    asm volatile("st.shared::cluster.b32 [%0], %1;" :: "r"(a), "r"(v) : "memory");
}
__device__ __forceinline__ void cluster_sync_() {
    asm volatile("barrier.cluster.arrive.aligned;" ::: "memory");
    asm volatile("barrier.cluster.wait.aligned;" ::: "memory");
}

// -------------------- pack xyz --------------------
__global__ void pack_kernel(const float* __restrict__ pts) {
    int i = blockIdx.x * blockDim.x + threadIdx.x;
    if (i < B_ * N_) {
        const float* p = pts + (size_t)i * C_;
        float x = p[0], y = p[1], z = p[2];
        g_xyz[i] = make_float4(x, y, z, x * x + y * y + z * z);
    }
}

// -------------------- FPS: 4-CTA cluster per batch, DSMEM candidate exchange ----
// smem float layout: sx[4096] sy[4096] sz[4096] rd[32] ri[32] cand_d cand_i
//                    mail[2 buffers][ d[4] i[4] x[4] y[4] z[4] ]
#define FPS_MAIL0 (3 * FPS_P + 64 + 2)
__global__ void __launch_bounds__(1024, 1) __cluster_dims__(4, 1, 1)
fps_kernel(float* centers_out) {
    extern __shared__ float fsm[];
    float* sx = fsm;
    float* sy = fsm + FPS_P;
    float* sz = fsm + 2 * FPS_P;
    float* rd = fsm + 3 * FPS_P;           // 32
    int*   ri = (int*)(rd + 32);           // 32
    float* cand_d = fsm + 3 * FPS_P + 64;  // 1
    int*   cand_i = (int*)(cand_d + 1);    // 1

    const int b = blockIdx.x >> 2;
    const uint32_t rank = blockIdx.x & 3;
    const int tid = threadIdx.x;
    const int lane = tid & 31, wid = tid >> 5;
    const uint32_t mail_bytes = smem_u32(fsm + FPS_MAIL0);

    for (int n = tid; n < FPS_P; n += 1024) {
        float4 q = g_xyz[b * N_ + rank * FPS_P + n];
        sx[n] = q.x; sy[n] = q.y; sz[n] = q.z;
    }
    float dist[4];
#pragma unroll
    for (int j = 0; j < 4; j++) dist[j] = 1e10f;
    __syncthreads();

    // initial broadcast of point 0 coords (owner rank 0) into mailbox buffer 1 slot 0
    if (rank == 0 && tid == 0) {
        float x = sx[0], y = sy[0], z = sz[0];
        for (uint32_t r = 0; r < 4; r++) {
            uint32_t a = mapa_sh(mail_bytes + 80, r);   // buffer 1
            stsc_f(a + 32, x);    // x slot0
            stsc_f(a + 48, y);
            stsc_f(a + 64, z);
        }
    }
    cluster_sync_();
    int far = 0;
    float cx = fsm[FPS_MAIL0 + 20 + 8];
    float cy = fsm[FPS_MAIL0 + 20 + 12];
    float cz = fsm[FPS_MAIL0 + 20 + 16];

    for (int it = 0; it < M_; ++it) {
        if (rank == 0 && tid == 0) {
            g_center_idx[b * M_ + it] = far;
            float* gc = g_centers + (size_t)(b * M_ + it) * 3;
            gc[0] = cx; gc[1] = cy; gc[2] = cz;
            if (centers_out) {
                float* oc = centers_out + (size_t)(b * M_ + it) * 3;
                oc[0] = cx; oc[1] = cy; oc[2] = cz;
            }
        }
        float bd = -1.0f; int bi = 0x7fffffff;
#pragma unroll
        for (int j = 0; j < 4; j++) {
            int n = j * 1024 + tid;
            float dx = sx[n] - cx, dy = sy[n] - cy, dz = sz[n] - cz;
            float d = dx * dx + dy * dy + dz * dz;
            float nd = fminf(dist[j], d);
            dist[j] = nd;
            if (nd > bd) { bd = nd; bi = n; }
        }
#pragma unroll
        for (int off = 16; off; off >>= 1) {
            float od = __shfl_down_sync(0xffffffffu, bd, off);
            int   oi = __shfl_down_sync(0xffffffffu, bi, off);
            if (od > bd || (od == bd && oi < bi)) { bd = od; bi = oi; }
        }
        if (lane == 0) { rd[wid] = bd; ri[wid] = bi; }
        __syncthreads();
        if (wid == 0) {
            float vb = rd[lane]; int vi = ri[lane];
#pragma unroll
            for (int off = 16; off; off >>= 1) {
                float od = __shfl_down_sync(0xffffffffu, vb, off);
                int   oi = __shfl_down_sync(0xffffffffu, vi, off);
                if (od > vb || (od == vb && oi < vi)) { vb = od; vi = oi; }
            }
            if (lane == 0) { *cand_d = vb; *cand_i = vi; }
        }
        __syncthreads();
        const int p = it & 1;
        if (tid == 0) {
            float d = *cand_d;
            int li = *cand_i;
            int gi = (int)rank * FPS_P + li;
            float x = sx[li], y = sy[li], z = sz[li];
            for (uint32_t r = 0; r < 4; r++) {
                uint32_t a = mapa_sh(mail_bytes + p * 80 + rank * 4, r);
                stsc_f(a, d);
                stsc_i(a + 16, gi);
                stsc_f(a + 32, x);
                stsc_f(a + 48, y);
                stsc_f(a + 64, z);
            }
        }
        cluster_sync_();
        // pick winner among 4 slots (ties: lower global index)
        const float* md = fsm + FPS_MAIL0 + p * 20;
        const int*   mi = (const int*)(md + 4);
        float wd = md[0]; int wi = mi[0]; int ws = 0;
#pragma unroll
        for (int s = 1; s < 4; s++) {
            float d = md[s]; int i = mi[s];
            if (d > wd || (d == wd && i < wi)) { wd = d; wi = i; ws = s; }
        }
        far = wi;
        cx = md[8 + ws]; cy = md[12 + ws]; cz = md[16 + ws];
    }
}

// -------------------- kNN (exact radix select, lowest-index ties) --------------------
__global__ void __launch_bounds__(256) knn_kernel() {
    extern __shared__ float ksm[];
    float* d2s   = ksm;                      // N_
    int*   hist  = (int*)(ksm + N_);         // 2048
    int*   scansm = hist + 2048;             // 256
    int*   eql   = scansm + 256;             // 64
    int*   ctrs  = eql + 64;                 // 4

    const int bid = blockIdx.x;
    const int b = bid >> 9;
    const int tid = threadIdx.x;

    float cx = g_centers[bid * 3 + 0];
    float cy = g_centers[bid * 3 + 1];
    float cz = g_centers[bid * 3 + 2];
    float cc2 = cx * cx + cy * cy + cz * cz;

    for (int n = tid; n < N_; n += 256) {
        float4 q = g_xyz[b * N_ + n];
        float dot = cx * q.x + cy * q.y + cz * q.z;
        d2s[n] = cc2 - 2.0f * dot + q.w;
    }
    __syncthreads();

    unsigned prefix = 0u, pmask = 0u;
    int kk = K_;
    for (int lvl = 0; lvl < 3; ++lvl) {
        const int sh = (lvl == 0) ? 21 : ((lvl == 1) ? 10 : 0);
        const int nb = (lvl == 2) ? 1024 : 2048;
        for (int i = tid; i < 2048; i += 256) hist[i] = 0;
        __syncthreads();
        for (int n = tid; n < N_; n += 256) {
            unsigned u = okey(d2s[n]);
            if ((u & pmask) == prefix)
                atomicAdd(&hist[(u >> sh) & (unsigned)(nb - 1)], 1);
        }
        __syncthreads();
        const int per = nb / 256;
        int s = 0;
        for (int t = 0; t < per; ++t) s += hist[tid * per + t];
        scansm[tid] = s;
        __syncthreads();
        for (int off = 1; off < 256; off <<= 1) {
            int v = (tid >= off) ? scansm[tid - off] : 0;
            __syncthreads();
            scansm[tid] += v;
            __syncthreads();
        }
        int excl = scansm[tid] - s;
        if (excl < kk && excl + s >= kk) {
            int cum = excl;
            for (int t = 0; t < per; ++t) {
                int c = hist[tid * per + t];
                if (cum + c >= kk) { ctrs[2] = tid * per + t; ctrs[3] = kk - cum; break; }
                cum += c;
            }
        }
        __syncthreads();
        prefix |= ((unsigned)ctrs[2]) << sh;
        pmask  |= ((unsigned)(nb - 1)) << sh;
        kk = ctrs[3];
        __syncthreads();
    }
    if (tid == 0) { ctrs[0] = 0; ctrs[1] = 0; }
    __syncthreads();
    int* gout = g_gidx + (size_t)bid * K_;
    for (int n = tid; n < N_; n += 256) {
        unsigned u = okey(d2s[n]);
        if (u < prefix) {
            int p = atomicAdd(&ctrs[0], 1);
            gout[p] = n;
        } else if (u == prefix) {
            int e = atomicAdd(&ctrs[1], 1);
            if (e < 64) eql[e] = n;
        }
    }
    __syncthreads();
    if (tid == 0) {
        int less = ctrs[0];
        int eq = ctrs[1];
        int need = K_ - less;
        if (eq <= 64) {
            for (int s2 = 0; s2 < need; ++s2) {
                int mb = 0x7fffffff, mi = 0;
                for (int t = 0; t < eq; ++t)
                    if (eql[t] < mb) { mb = eql[t]; mi = t; }
                gout[less + s2] = mb;
                eql[mi] = 0x7fffffff;
            }
        } else {
            int c = 0;
            for (int n = 0; n < N_ && c < need; ++n)
                if (okey(d2s[n]) == prefix) { gout[less + c] = n; ++c; }
        }
    }
}

// -------------------- fused encoder (f32x2, 2 groups / 64 rows per CTA) ----------
// 256 threads, 8 warps; warp w owns rows 8w..8w+7 as 4 f32x2 row-pairs.
// Activations transposed in SMEM: act[c*66 + r].
#define AST 66

template<int CIN, int DOUT, int JT>
__device__ __forceinline__ void enc_pass(
    const float* __restrict__ in, float* __restrict__ out,
    const float* __restrict__ w, int colbase,
    const float* __restrict__ bias,
    const float* __restrict__ gg, const float* __restrict__ bb,
    const float* __restrict__ mm, const float* __restrict__ vv,
    int warp, int lane)
{
    unsigned long long acc[4][JT];
#pragma unroll
    for (int p = 0; p < 4; p++)
#pragma unroll
        for (int j = 0; j < JT; j++) acc[p][j] = 0ull;
    const int rbase = warp * 8;
    const float* wp = w + colbase + lane;
    float wf[JT];
#pragma unroll
    for (int j = 0; j < JT; j++) wf[j] = __ldg(wp + 32 * j);
#pragma unroll 4
    for (int c = 0; c < CIN; ++c) {
        float wn[JT];
        if (c + 1 < CIN) {
            const float* np = wp + (size_t)(c + 1) * DOUT;
#pragma unroll
            for (int j = 0; j < JT; j++) wn[j] = __ldg(np + 32 * j);
        }
        const float* inc = in + c * AST + rbase;
        unsigned long long a0 = *(const unsigned long long*)(inc + 0);
        unsigned long long a1 = *(const unsigned long long*)(inc + 2);
        unsigned long long a2 = *(const unsigned long long*)(inc + 4);
        unsigned long long a3 = *(const unsigned long long*)(inc + 6);
#pragma unroll
        for (int j = 0; j < JT; j++) {
            unsigned long long wd = dupf(wf[j]);
            acc[0][j] = ffma2(a0, wd, acc[0][j]);
            acc[1][j] = ffma2(a1, wd, acc[1][j]);
            acc[2][j] = ffma2(a2, wd, acc[2][j]);
            acc[3][j] = ffma2(a3, wd, acc[3][j]);
        }
        if (c + 1 < CIN) {
#pragma unroll
            for (int j = 0; j < JT; j++) wf[j] = wn[j];
        }
    }
#pragma unroll
    for (int j = 0; j < JT; j++) {
        int col = colbase + lane + 32 * j;
        float bj  = __ldg(bias + col);
        float sc  = __ldg(gg + col) * rsqrtf(__ldg(vv + col) + 1e-5f);
        float mj  = __ldg(mm + col);
        float bet = __ldg(bb + col);
        float* op = out + col * AST + rbase;
#pragma unroll
        for (int p = 0; p < 4; p++) {
            float2 v = unpk(acc[p][j]);
            float lo = fmaxf((v.x + bj - mj) * sc + bet, 0.0f);
            float hi = fmaxf((v.y + bj - mj) * sc + bet, 0.0f);
            *(unsigned long long*)(op + 2 * p) = pack2(lo, hi);
        }
    }
}

template<int CIN, int JT>
__device__ __forceinline__ void enc_l4(
    const float* __restrict__ in, const float* __restrict__ w, int colbase,
    const float* __restrict__ bias, float* __restrict__ maxb,
    int warp, int lane)
{
    unsigned long long acc[4][JT];
#pragma unroll
    for (int p = 0; p < 4; p++)
#pragma unroll
        for (int j = 0; j < JT; j++) acc[p][j] = 0ull;
    const int rbase = warp * 8;
    const float* wp = w + colbase + lane;
    float wf[JT];
#pragma unroll
    for (int j = 0; j < JT; j++) wf[j] = __ldg(wp + 32 * j);
#pragma unroll 2
    for (int c = 0; c < CIN; ++c) {
        float wn[JT];
        if (c + 1 < CIN) {
            const float* np = wp + (size_t)(c + 1) * 384;
#pragma unroll
            for (int j = 0; j < JT; j++) wn[j] = __ldg(np + 32 * j);
        }
        const float* inc = in + c * AST + rbase;
        unsigned long long a0 = *(const unsigned long long*)(inc + 0);
        unsigned long long a1 = *(const unsigned long long*)(inc + 2);
        unsigned long long a2 = *(const unsigned long long*)(inc + 4);
        unsigned long long a3 = *(const unsigned long long*)(inc + 6);
#pragma unroll
        for (int j = 0; j < JT; j++) {
            unsigned long long wd = dupf(wf[j]);
            acc[0][j] = ffma2(a0, wd, acc[0][j]);
            acc[1][j] = ffma2(a1, wd, acc[1][j]);
            acc[2][j] = ffma2(a2, wd, acc[2][j]);
            acc[3][j] = ffma2(a3, wd, acc[3][j]);
        }
        if (c + 1 < CIN) {
#pragma unroll
            for (int j = 0; j < JT; j++) wf[j] = wn[j];
        }
    }
#pragma unroll
    for (int j = 0; j < JT; j++) {
        int col = colbase + lane + 32 * j;
        float mx = -1e30f;
#pragma unroll
        for (int p = 0; p < 4; p++) {
            float2 v = unpk(acc[p][j]);
            mx = fmaxf(mx, fmaxf(v.x, v.y));
        }
        maxb[warp * 384 + col] = mx + __ldg(bias + col);
    }
}

// SMEM floats: buf0 @0 (9*66=594), bufA @594 (256*66=16896), bufB @17490 (128*66=8448)
// maxb aliases bufB during layer 4 (needs 8*384=3072 <= 8448).
__global__ void __launch_bounds__(256, 2) encoder_kernel(
    const float* __restrict__ pts,
    const float* __restrict__ w1, const float* __restrict__ b1,
    const float* __restrict__ g1, const float* __restrict__ be1,
    const float* __restrict__ m1, const float* __restrict__ v1,
    const float* __restrict__ w2, const float* __restrict__ b2,
    const float* __restrict__ g2, const float* __restrict__ be2,
    const float* __restrict__ m2, const float* __restrict__ v2,
    const float* __restrict__ w3, const float* __restrict__ b3,
    const float* __restrict__ g3, const float* __restrict__ be3,
    const float* __restrict__ m3, const float* __restrict__ v3,
    const float* __restrict__ w4, const float* __restrict__ b4,
    float* __restrict__ tokens)
{
    extern __shared__ float esm[];
    float* buf0 = esm;
    float* bufA = esm + 594;
    float* bufB = esm + 594 + 16896;
    float* maxb = bufB;                       // alias (bufB dead during L4)

    const int tid = threadIdx.x;
    const int warp = tid >> 5, lane = tid & 31;

    if (tid < 64) {
        int gid2 = blockIdx.x * 2 + (tid >> 5);
        int b = gid2 >> 9;
        int n = g_gidx[(size_t)gid2 * K_ + (tid & 31)];
        const float* p = pts + (size_t)(b * N_ + n) * C_;
        float cx = g_centers[gid2 * 3 + 0];
        float cy = g_centers[gid2 * 3 + 1];
        float cz = g_centers[gid2 * 3 + 2];
        float x = p[0], y = p[1], z = p[2];
        buf0[0 * AST + tid] = x - cx;
        buf0[1 * AST + tid] = y - cy;
        buf0[2 * AST + tid] = z - cz;
        buf0[3 * AST + tid] = x;
        buf0[4 * AST + tid] = y;
        buf0[5 * AST + tid] = z;
        buf0[6 * AST + tid] = p[3];
        buf0[7 * AST + tid] = p[4];
        buf0[8 * AST + tid] = p[5];
    }
    __syncthreads();
    enc_pass<9, 64, 2>(buf0, bufA, w1, 0, b1, g1, be1, m1, v1, warp, lane);
    __syncthreads();
    enc_pass<64, 128, 4>(bufA, bufB, w2, 0, b2, g2, be2, m2, v2, warp, lane);
    __syncthreads();
    enc_pass<128, 256, 4>(bufB, bufA, w3, 0,   b3, g3, be3, m3, v3, warp, lane);
    enc_pass<128, 256, 4>(bufB, bufA, w3, 128, b3, g3, be3, m3, v3, warp, lane);
    __syncthreads();
    enc_l4<256, 6>(bufA, w4, 0,   b4, maxb, warp, lane);
    enc_l4<256, 6>(bufA, w4, 192, b4, maxb, warp, lane);
    __syncthreads();
    for (int i = tid; i < 768; i += 256) {
        int g = i / 384, col = i - g * 384;
        float mx = maxb[(4 * g) * 384 + col];
#pragma unroll
        for (int w = 1; w < 4; ++w) mx = fmaxf(mx, maxb[(4 * g + w) * 384 + col]);
        tokens[(size_t)(blockIdx.x * 2 + g) * 384 + col] = mx;
    }
}

// -------------------- positional MLP (exact gelu) --------------------
__global__ void __launch_bounds__(128) pos_kernel(
    const float* __restrict__ pw1, const float* __restrict__ pb1,
    const float* __restrict__ pw2, const float* __restrict__ pb2,
    float* __restrict__ tokens)
{
    __shared__ float h[128];
    const int gid = blockIdx.x;
    const int tid = threadIdx.x;
    float cx = g_centers[gid * 3 + 0];
    float cy = g_centers[gid * 3 + 1];
    float cz = g_centers[gid * 3 + 2];
    float t = cx * __ldg(pw1 + tid) + cy * __ldg(pw1 + 128 + tid)
            + cz * __ldg(pw1 + 256 + tid) + __ldg(pb1 + tid);
    float ge = 0.5f * t * (1.0f + erff(t * 0.70710678118654752f));
    h[tid] = ge;
    __syncthreads();
#pragma unroll
    for (int jj = 0; jj < 3; ++jj) {
        int col = tid + jj * 128;
        float acc = __ldg(pb2 + col);
#pragma unroll 4
        for (int c = 0; c < 128; ++c)
            acc = fmaf(h[c], __ldg(pw2 + (size_t)c * 384 + col), acc);
        tokens[(size_t)gid * 384 + col] += acc;
    }
}

// -------------------- launch --------------------
extern "C" void kernel_launch(void* const* d_in, const int* in_sizes, int n_in,
                              void* d_out, int out_size)
{
    const float* pts = (const float*)d_in[0];
    const float* w1 = (const float*)d_in[1],  *b1 = (const float*)d_in[2];
    const float* g1 = (const float*)d_in[3],  *be1 = (const float*)d_in[4];
    const float* m1 = (const float*)d_in[5],  *v1 = (const float*)d_in[6];
    const float* w2 = (const float*)d_in[7],  *b2 = (const float*)d_in[8];
    const float* g2 = (const float*)d_in[9],  *be2 = (const float*)d_in[10];
    const float* m2 = (const float*)d_in[11], *v2 = (const float*)d_in[12];
    const float* w3 = (const float*)d_in[13], *b3 = (const float*)d_in[14];
    const float* g3 = (const float*)d_in[15], *be3 = (const float*)d_in[16];
    const float* m3 = (const float*)d_in[17], *v3 = (const float*)d_in[18];
    const float* w4 = (const float*)d_in[19], *b4 = (const float*)d_in[20];
    const float* pw1 = (const float*)d_in[21], *pb1 = (const float*)d_in[22];
    const float* pw2 = (const float*)d_in[23], *pb2 = (const float*)d_in[24];

    float* out = (float*)d_out;
    float* tokens = out;
    float* centers_out =
        (out_size >= B_ * M_ * 384 + B_ * M_ * 3) ? (out + (size_t)B_ * M_ * 384)
                                                  : nullptr;

    const int FPS_SMEM = (3 * FPS_P + 64 + 2 + 40) * 4;        // 49,624 B
    const int KNN_SMEM = (N_ + 2048 + 256 + 64 + 8) * 4;       // ~75 KB
    const int ENC_SMEM = (594 + 16896 + 8448) * 4;             // 103,752 B

    cudaFuncSetAttribute(fps_kernel, cudaFuncAttributeMaxDynamicSharedMemorySize, FPS_SMEM);
    cudaFuncSetAttribute(knn_kernel, cudaFuncAttributeMaxDynamicSharedMemorySize, KNN_SMEM);
    cudaFuncSetAttribute(encoder_kernel, cudaFuncAttributeMaxDynamicSharedMemorySize, ENC_SMEM);

    pack_kernel<<<(B_ * N_ + 255) / 256, 256>>>(pts);
    fps_kernel<<<B_ * 4, 1024, FPS_SMEM>>>(centers_out);
    knn_kernel<<<B_ * M_, 256, KNN_SMEM>>>();
    encoder_kernel<<<B_ * M_ / 2, 256, ENC_SMEM>>>(
        pts, w1, b1, g1, be1, m1, v1, w2, b2, g2, be2, m2, v2,
        w3, b3, g3, be3, m3, v3, w4, b4, tokens);
    pos_kernel<<<B_ * M_, 128>>>(pw1, pb1, pw2, pb2, tokens);
}

// round 5
// speedup vs baseline: 1.1374x; 1.0041x over previous
#include <cuda_runtime.h>
#include <math.h>
#include <stdint.h>

#define B_ 8
#define N_ 16384
#define M_ 512
#define K_ 32
#define C_ 6
#define FPS_P 4096       // points per FPS CTA (N_/4)

// -------------------- scratch (no allocations allowed) --------------------
__device__ int    g_center_idx[B_ * M_];
__device__ float  g_centers[B_ * M_ * 3];
__device__ int    g_gidx[B_ * M_ * K_];
__device__ float4 g_xyz[B_ * N_];
// duplicated weights: wd[c][2j] = wd[c][2j+1] = w[c][j]
__device__ __align__(16) float g_wd1[9 * 128];
__device__ __align__(16) float g_wd2[64 * 256];
__device__ __align__(16) float g_wd3[128 * 512];
__device__ __align__(16) float g_wd4[256 * 768];

// -------------------- helpers --------------------
__device__ __forceinline__ unsigned okey(float f) {
    unsigned u = __float_as_uint(f);
    unsigned mask = (u & 0x80000000u) ? 0xFFFFFFFFu : 0x80000000u;
    return u ^ mask;
}
__device__ __forceinline__ unsigned long long ffma2(
    unsigned long long a, unsigned long long b, unsigned long long c) {
    unsigned long long d;
    asm("fma.rn.f32x2 %0, %1, %2, %3;" : "=l"(d) : "l"(a), "l"(b), "l"(c));
    return d;
}
__device__ __forceinline__ unsigned long long pack2(float lo, float hi) {
    unsigned long long d;
    asm("mov.b64 %0, {%1, %2};" : "=l"(d) : "f"(lo), "f"(hi));
    return d;
}
__device__ __forceinline__ float2 unpk(unsigned long long v) {
    float lo, hi;
    asm("mov.b64 {%0, %1}, %2;" : "=f"(lo), "=f"(hi) : "l"(v));
    return make_float2(lo, hi);
}
__device__ __forceinline__ uint32_t smem_u32(const void* p) {
    uint32_t a;
    asm("{ .reg .u64 t; cvta.to.shared.u64 t, %1; cvt.u32.u64 %0, t; }" : "=r"(a) : "l"(p));
    return a;
}
__device__ __forceinline__ uint32_t mapa_sh(uint32_t addr, uint32_t rank) {
    uint32_t r;
    asm("mapa.shared::cluster.u32 %0, %1, %2;" : "=r"(r) : "r"(addr), "r"(rank));
    return r;
}
__device__ __forceinline__ void stsc_f(uint32_t a, float v) {
    asm volatile("st.shared::cluster.f32 [%0], %1;" :: "r"(a), "f"(v) : "memory");
}
__device__ __forceinline__ void stsc_i(uint32_t a, int v) {
    asm volatile("st.shared::cluster.b32 [%0], %1;" :: "r"(a), "r"(v) : "memory");
}
__device__ __forceinline__ void cluster_sync_() {
    asm volatile("barrier.cluster.arrive.aligned;" ::: "memory");
    asm volatile("barrier.cluster.wait.aligned;" ::: "memory");
}

// -------------------- weight duplication prep --------------------
__global__ void dup_kernel(const float* __restrict__ src, float* __restrict__ dst,
                           int total, int D) {
    int i = blockIdx.x * blockDim.x + threadIdx.x;
    if (i < total) {
        int c = i / D, j = i - c * D;
        float v = src[i];
        dst[(size_t)c * 2 * D + 2 * j]     = v;
        dst[(size_t)c * 2 * D + 2 * j + 1] = v;
    }
}

// -------------------- pack xyz --------------------
__global__ void pack_kernel(const float* __restrict__ pts) {
    int i = blockIdx.x * blockDim.x + threadIdx.x;
    if (i < B_ * N_) {
        const float* p = pts + (size_t)i * C_;
        float x = p[0], y = p[1], z = p[2];
        g_xyz[i] = make_float4(x, y, z, x * x + y * y + z * z);
    }
}

// -------------------- FPS: 4-CTA cluster per batch, DSMEM candidate exchange ----
#define FPS_MAIL0 (3 * FPS_P + 64 + 2)
__global__ void __launch_bounds__(1024, 1) __cluster_dims__(4, 1, 1)
fps_kernel(float* centers_out) {
    extern __shared__ float fsm[];
    float* sx = fsm;
    float* sy = fsm + FPS_P;
    float* sz = fsm + 2 * FPS_P;
    float* rd = fsm + 3 * FPS_P;           // 32
    int*   ri = (int*)(rd + 32);           // 32
    float* cand_d = fsm + 3 * FPS_P + 64;  // 1
    int*   cand_i = (int*)(cand_d + 1);    // 1

    const int b = blockIdx.x >> 2;
    const uint32_t rank = blockIdx.x & 3;
    const int tid = threadIdx.x;
    const int lane = tid & 31, wid = tid >> 5;
    const uint32_t mail_bytes = smem_u32(fsm + FPS_MAIL0);

    for (int n = tid; n < FPS_P; n += 1024) {
        float4 q = g_xyz[b * N_ + rank * FPS_P + n];
        sx[n] = q.x; sy[n] = q.y; sz[n] = q.z;
    }
    float dist[4];
#pragma unroll
    for (int j = 0; j < 4; j++) dist[j] = 1e10f;
    __syncthreads();

    if (rank == 0 && tid == 0) {
        float x = sx[0], y = sy[0], z = sz[0];
        for (uint32_t r = 0; r < 4; r++) {
            uint32_t a = mapa_sh(mail_bytes + 80, r);   // buffer 1
            stsc_f(a + 32, x);
            stsc_f(a + 48, y);
            stsc_f(a + 64, z);
        }
    }
    cluster_sync_();
    int far = 0;
    float cx = fsm[FPS_MAIL0 + 20 + 8];
    float cy = fsm[FPS_MAIL0 + 20 + 12];
    float cz = fsm[FPS_MAIL0 + 20 + 16];

    for (int it = 0; it < M_; ++it) {
        if (rank == 0 && tid == 0) {
            g_center_idx[b * M_ + it] = far;
            float* gc = g_centers + (size_t)(b * M_ + it) * 3;
            gc[0] = cx; gc[1] = cy; gc[2] = cz;
            if (centers_out) {
                float* oc = centers_out + (size_t)(b * M_ + it) * 3;
                oc[0] = cx; oc[1] = cy; oc[2] = cz;
            }
        }
        float bd = -1.0f; int bi = 0x7fffffff;
#pragma unroll
        for (int j = 0; j < 4; j++) {
            int n = j * 1024 + tid;
            float dx = sx[n] - cx, dy = sy[n] - cy, dz = sz[n] - cz;
            float d = dx * dx + dy * dy + dz * dz;
            float nd = fminf(dist[j], d);
            dist[j] = nd;
            if (nd > bd) { bd = nd; bi = n; }
        }
#pragma unroll
        for (int off = 16; off; off >>= 1) {
            float od = __shfl_down_sync(0xffffffffu, bd, off);
            int   oi = __shfl_down_sync(0xffffffffu, bi, off);
            if (od > bd || (od == bd && oi < bi)) { bd = od; bi = oi; }
        }
        if (lane == 0) { rd[wid] = bd; ri[wid] = bi; }
        __syncthreads();
        if (wid == 0) {
            float vb = rd[lane]; int vi = ri[lane];
#pragma unroll
            for (int off = 16; off; off >>= 1) {
                float od = __shfl_down_sync(0xffffffffu, vb, off);
                int   oi = __shfl_down_sync(0xffffffffu, vi, off);
                if (od > vb || (od == vb && oi < vi)) { vb = od; vi = oi; }
            }
            if (lane == 0) { *cand_d = vb; *cand_i = vi; }
        }
        __syncthreads();
        const int p = it & 1;
        if (tid == 0) {
            float d = *cand_d;
            int li = *cand_i;
            int gi = (int)rank * FPS_P + li;
            float x = sx[li], y = sy[li], z = sz[li];
            for (uint32_t r = 0; r < 4; r++) {
                uint32_t a = mapa_sh(mail_bytes + p * 80 + rank * 4, r);
                stsc_f(a, d);
                stsc_i(a + 16, gi);
                stsc_f(a + 32, x);
                stsc_f(a + 48, y);
                stsc_f(a + 64, z);
            }
        }
        cluster_sync_();
        const float* md = fsm + FPS_MAIL0 + p * 20;
        const int*   mi = (const int*)(md + 4);
        float wd = md[0]; int wi = mi[0]; int ws = 0;
#pragma unroll
        for (int s = 1; s < 4; s++) {
            float d = md[s]; int i = mi[s];
            if (d > wd || (d == wd && i < wi)) { wd = d; wi = i; ws = s; }
        }
        far = wi;
        cx = md[8 + ws]; cy = md[12 + ws]; cz = md[16 + ws];
    }
}

// -------------------- kNN (exact radix select, lowest-index ties) --------------------
__global__ void __launch_bounds__(256) knn_kernel() {
    extern __shared__ float ksm[];
    float* d2s   = ksm;                      // N_
    int*   hist  = (int*)(ksm + N_);         // 2048
    int*   scansm = hist + 2048;             // 256
    int*   eql   = scansm + 256;             // 64
    int*   ctrs  = eql + 64;                 // 4

    const int bid = blockIdx.x;
    const int b = bid >> 9;
    const int tid = threadIdx.x;

    float cx = g_centers[bid * 3 + 0];
    float cy = g_centers[bid * 3 + 1];
    float cz = g_centers[bid * 3 + 2];
    float cc2 = cx * cx + cy * cy + cz * cz;

    for (int n = tid; n < N_; n += 256) {
        float4 q = g_xyz[b * N_ + n];
        float dot = cx * q.x + cy * q.y + cz * q.z;
        d2s[n] = cc2 - 2.0f * dot + q.w;
    }
    __syncthreads();

    unsigned prefix = 0u, pmask = 0u;
    int kk = K_;
    for (int lvl = 0; lvl < 3; ++lvl) {
        const int sh = (lvl == 0) ? 21 : ((lvl == 1) ? 10 : 0);
        const int nb = (lvl == 2) ? 1024 : 2048;
        for (int i = tid; i < 2048; i += 256) hist[i] = 0;
        __syncthreads();
        for (int n = tid; n < N_; n += 256) {
            unsigned u = okey(d2s[n]);
            if ((u & pmask) == prefix)
                atomicAdd(&hist[(u >> sh) & (unsigned)(nb - 1)], 1);
        }
        __syncthreads();
        const int per = nb / 256;
        int s = 0;
        for (int t = 0; t < per; ++t) s += hist[tid * per + t];
        scansm[tid] = s;
        __syncthreads();
        for (int off = 1; off < 256; off <<= 1) {
            int v = (tid >= off) ? scansm[tid - off] : 0;
            __syncthreads();
            scansm[tid] += v;
            __syncthreads();
        }
        int excl = scansm[tid] - s;
        if (excl < kk && excl + s >= kk) {
            int cum = excl;
            for (int t = 0; t < per; ++t) {
                int c = hist[tid * per + t];
                if (cum + c >= kk) { ctrs[2] = tid * per + t; ctrs[3] = kk - cum; break; }
                cum += c;
            }
        }
        __syncthreads();
        prefix |= ((unsigned)ctrs[2]) << sh;
        pmask  |= ((unsigned)(nb - 1)) << sh;
        kk = ctrs[3];
        __syncthreads();
    }
    if (tid == 0) { ctrs[0] = 0; ctrs[1] = 0; }
    __syncthreads();
    int* gout = g_gidx + (size_t)bid * K_;
    for (int n = tid; n < N_; n += 256) {
        unsigned u = okey(d2s[n]);
        if (u < prefix) {
            int p = atomicAdd(&ctrs[0], 1);
            gout[p] = n;
        } else if (u == prefix) {
            int e = atomicAdd(&ctrs[1], 1);
            if (e < 64) eql[e] = n;
        }
    }
    __syncthreads();
    if (tid == 0) {
        int less = ctrs[0];
        int eq = ctrs[1];
        int need = K_ - less;
        if (eq <= 64) {
            for (int s2 = 0; s2 < need; ++s2) {
                int mb = 0x7fffffff, mi = 0;
                for (int t = 0; t < eq; ++t)
                    if (eql[t] < mb) { mb = eql[t]; mi = t; }
                gout[less + s2] = mb;
                eql[mi] = 0x7fffffff;
            }
        } else {
            int c = 0;
            for (int n = 0; n < N_ && c < need; ++n)
                if (okey(d2s[n]) == prefix) { gout[less + c] = n; ++c; }
        }
    }
}

// -------------------- fused encoder (f32x2, dup'd weights, 64 rows/CTA) ----------
// 256 threads, 8 warps; warp w owns rows 8w..8w+7 as 4 f32x2 row-pairs.
// Activations transposed in SMEM: act[c*66 + r]. Weights pre-duplicated in GMEM:
// one LDG.64 yields (w,w) -> zero ALU in the inner loop.
#define AST 66

template<int CIN, int DOUT, int JT>
__device__ __forceinline__ void enc_pass(
    const float* __restrict__ in, float* __restrict__ out,
    const float* __restrict__ wd, int colbase,
    const float* __restrict__ bias,
    const float* __restrict__ gg, const float* __restrict__ bb,
    const float* __restrict__ mm, const float* __restrict__ vv,
    int warp, int lane)
{
    unsigned long long acc[4][JT];
#pragma unroll
    for (int p = 0; p < 4; p++)
#pragma unroll
        for (int j = 0; j < JT; j++) acc[p][j] = 0ull;
    const int rbase = warp * 8;
    const unsigned long long* wp =
        (const unsigned long long*)(wd + 2 * (colbase + lane));
#pragma unroll 4
    for (int c = 0; c < CIN; ++c) {
        const float* inc = in + c * AST + rbase;
        unsigned long long a0 = *(const unsigned long long*)(inc + 0);
        unsigned long long a1 = *(const unsigned long long*)(inc + 2);
        unsigned long long a2 = *(const unsigned long long*)(inc + 4);
        unsigned long long a3 = *(const unsigned long long*)(inc + 6);
        const unsigned long long* wc = wp + (size_t)c * DOUT;   // DOUT u64 per row
#pragma unroll
        for (int j = 0; j < JT; j++) {
            unsigned long long w = __ldg(wc + 32 * j);
            acc[0][j] = ffma2(a0, w, acc[0][j]);
            acc[1][j] = ffma2(a1, w, acc[1][j]);
            acc[2][j] = ffma2(a2, w, acc[2][j]);
            acc[3][j] = ffma2(a3, w, acc[3][j]);
        }
    }
#pragma unroll
    for (int j = 0; j < JT; j++) {
        int col = colbase + lane + 32 * j;
        float bj  = __ldg(bias + col);
        float sc  = __ldg(gg + col) * rsqrtf(__ldg(vv + col) + 1e-5f);
        float mj  = __ldg(mm + col);
        float bet = __ldg(bb + col);
        float* op = out + col * AST + rbase;
#pragma unroll
        for (int p = 0; p < 4; p++) {
            float2 v = unpk(acc[p][j]);
            float lo = fmaxf((v.x + bj - mj) * sc + bet, 0.0f);
            float hi = fmaxf((v.y + bj - mj) * sc + bet, 0.0f);
            *(unsigned long long*)(op + 2 * p) = pack2(lo, hi);
        }
    }
}

template<int CIN, int JT>
__device__ __forceinline__ void enc_l4(
    const float* __restrict__ in, const float* __restrict__ wd, int colbase,
    const float* __restrict__ bias, float* __restrict__ maxb,
    int warp, int lane)
{
    unsigned long long acc[4][JT];
#pragma unroll
    for (int p = 0; p < 4; p++)
#pragma unroll
        for (int j = 0; j < JT; j++) acc[p][j] = 0ull;
    const int rbase = warp * 8;
    const unsigned long long* wp =
        (const unsigned long long*)(wd + 2 * (colbase + lane));
#pragma unroll 4
    for (int c = 0; c < CIN; ++c) {
        const float* inc = in + c * AST + rbase;
        unsigned long long a0 = *(const unsigned long long*)(inc + 0);
        unsigned long long a1 = *(const unsigned long long*)(inc + 2);
        unsigned long long a2 = *(const unsigned long long*)(inc + 4);
        unsigned long long a3 = *(const unsigned long long*)(inc + 6);
        const unsigned long long* wc = wp + (size_t)c * 384;
#pragma unroll
        for (int j = 0; j < JT; j++) {
            unsigned long long w = __ldg(wc + 32 * j);
            acc[0][j] = ffma2(a0, w, acc[0][j]);
            acc[1][j] = ffma2(a1, w, acc[1][j]);
            acc[2][j] = ffma2(a2, w, acc[2][j]);
            acc[3][j] = ffma2(a3, w, acc[3][j]);
        }
    }
#pragma unroll
    for (int j = 0; j < JT; j++) {
        int col = colbase + lane + 32 * j;
        float mx = -1e30f;
#pragma unroll
        for (int p = 0; p < 4; p++) {
            float2 v = unpk(acc[p][j]);
            mx = fmaxf(mx, fmaxf(v.x, v.y));
        }
        maxb[warp * 384 + col] = mx + __ldg(bias + col);
    }
}

// SMEM floats: buf0 @0 (9*66=594), bufA @594 (256*66=16896), bufB @17490 (128*66=8448)
__global__ void __launch_bounds__(256, 2) encoder_kernel(
    const float* __restrict__ pts,
    const float* __restrict__ b1,
    const float* __restrict__ g1, const float* __restrict__ be1,
    const float* __restrict__ m1, const float* __restrict__ v1,
    const float* __restrict__ b2,
    const float* __restrict__ g2, const float* __restrict__ be2,
    const float* __restrict__ m2, const float* __restrict__ v2,
    const float* __restrict__ b3,
    const float* __restrict__ g3, const float* __restrict__ be3,
    const float* __restrict__ m3, const float* __restrict__ v3,
    const float* __restrict__ b4,
    float* __restrict__ tokens)
{
    extern __shared__ float esm[];
    float* buf0 = esm;
    float* bufA = esm + 594;
    float* bufB = esm + 594 + 16896;
    float* maxb = bufB;                       // alias (bufB dead during L4)

    const int tid = threadIdx.x;
    const int warp = tid >> 5, lane = tid & 31;

    if (tid < 64) {
        int gid2 = blockIdx.x * 2 + (tid >> 5);
        int b = gid2 >> 9;
        int n = g_gidx[(size_t)gid2 * K_ + (tid & 31)];
        const float* p = pts + (size_t)(b * N_ + n) * C_;
        float cx = g_centers[gid2 * 3 + 0];
        float cy = g_centers[gid2 * 3 + 1];
        float cz = g_centers[gid2 * 3 + 2];
        float x = p[0], y = p[1], z = p[2];
        buf0[0 * AST + tid] = x - cx;
        buf0[1 * AST + tid] = y - cy;
        buf0[2 * AST + tid] = z - cz;
        buf0[3 * AST + tid] = x;
        buf0[4 * AST + tid] = y;
        buf0[5 * AST + tid] = z;
        buf0[6 * AST + tid] = p[3];
        buf0[7 * AST + tid] = p[4];
        buf0[8 * AST + tid] = p[5];
    }
    __syncthreads();
    enc_pass<9, 64, 2>(buf0, bufA, g_wd1, 0, b1, g1, be1, m1, v1, warp, lane);
    __syncthreads();
    enc_pass<64, 128, 4>(bufA, bufB, g_wd2, 0, b2, g2, be2, m2, v2, warp, lane);
    __syncthreads();
    enc_pass<128, 256, 4>(bufB, bufA, g_wd3, 0,   b3, g3, be3, m3, v3, warp, lane);
    enc_pass<128, 256, 4>(bufB, bufA, g_wd3, 128, b3, g3, be3, m3, v3, warp, lane);
    __syncthreads();
    enc_l4<256, 6>(bufA, g_wd4, 0,   b4, maxb, warp, lane);
    enc_l4<256, 6>(bufA, g_wd4, 192, b4, maxb, warp, lane);
    __syncthreads();
    for (int i = tid; i < 768; i += 256) {
        int g = i / 384, col = i - g * 384;
        float mx = maxb[(4 * g) * 384 + col];
#pragma unroll
        for (int w = 1; w < 4; ++w) mx = fmaxf(mx, maxb[(4 * g + w) * 384 + col]);
        tokens[(size_t)(blockIdx.x * 2 + g) * 384 + col] = mx;
    }
}

// -------------------- positional MLP (exact gelu) --------------------
__global__ void __launch_bounds__(128) pos_kernel(
    const float* __restrict__ pw1, const float* __restrict__ pb1,
    const float* __restrict__ pw2, const float* __restrict__ pb2,
    float* __restrict__ tokens)
{
    __shared__ float h[128];
    const int gid = blockIdx.x;
    const int tid = threadIdx.x;
    float cx = g_centers[gid * 3 + 0];
    float cy = g_centers[gid * 3 + 1];
    float cz = g_centers[gid * 3 + 2];
    float t = cx * __ldg(pw1 + tid) + cy * __ldg(pw1 + 128 + tid)
            + cz * __ldg(pw1 + 256 + tid) + __ldg(pb1 + tid);
    float ge = 0.5f * t * (1.0f + erff(t * 0.70710678118654752f));
    h[tid] = ge;
    __syncthreads();
#pragma unroll
    for (int jj = 0; jj < 3; ++jj) {
        int col = tid + jj * 128;
        float acc = __ldg(pb2 + col);
#pragma unroll 4
        for (int c = 0; c < 128; ++c)
            acc = fmaf(h[c], __ldg(pw2 + (size_t)c * 384 + col), acc);
        tokens[(size_t)gid * 384 + col] += acc;
    }
}

// -------------------- launch --------------------
extern "C" void kernel_launch(void* const* d_in, const int* in_sizes, int n_in,
                              void* d_out, int out_size)
{
    const float* pts = (const float*)d_in[0];
    const float* w1 = (const float*)d_in[1],  *b1 = (const float*)d_in[2];
    const float* g1 = (const float*)d_in[3],  *be1 = (const float*)d_in[4];
    const float* m1 = (const float*)d_in[5],  *v1 = (const float*)d_in[6];
    const float* w2 = (const float*)d_in[7],  *b2 = (const float*)d_in[8];
    const float* g2 = (const float*)d_in[9],  *be2 = (const float*)d_in[10];
    const float* m2 = (const float*)d_in[11], *v2 = (const float*)d_in[12];
    const float* w3 = (const float*)d_in[13], *b3 = (const float*)d_in[14];
    const float* g3 = (const float*)d_in[15], *be3 = (const float*)d_in[16];
    const float* m3 = (const float*)d_in[17], *v3 = (const float*)d_in[18];
    const float* w4 = (const float*)d_in[19], *b4 = (const float*)d_in[20];
    const float* pw1 = (const float*)d_in[21], *pb1 = (const float*)d_in[22];
    const float* pw2 = (const float*)d_in[23], *pb2 = (const float*)d_in[24];

    float* out = (float*)d_out;
    float* tokens = out;
    float* centers_out =
        (out_size >= B_ * M_ * 384 + B_ * M_ * 3) ? (out + (size_t)B_ * M_ * 384)
                                                  : nullptr;

    const int FPS_SMEM = (3 * FPS_P + 64 + 2 + 40) * 4;
    const int KNN_SMEM = (N_ + 2048 + 256 + 64 + 8) * 4;
    const int ENC_SMEM = (594 + 16896 + 8448) * 4;             // 103,752 B

    cudaFuncSetAttribute(fps_kernel, cudaFuncAttributeMaxDynamicSharedMemorySize, FPS_SMEM);
    cudaFuncSetAttribute(knn_kernel, cudaFuncAttributeMaxDynamicSharedMemorySize, KNN_SMEM);
    cudaFuncSetAttribute(encoder_kernel, cudaFuncAttributeMaxDynamicSharedMemorySize, ENC_SMEM);

    // weight duplication prep (runs in-graph; trivial cost)
    float* wd1; cudaGetSymbolAddress((void**)&wd1, g_wd1);
    float* wd2; cudaGetSymbolAddress((void**)&wd2, g_wd2);
    float* wd3; cudaGetSymbolAddress((void**)&wd3, g_wd3);
    float* wd4; cudaGetSymbolAddress((void**)&wd4, g_wd4);
    dup_kernel<<<(9 * 64 + 255) / 256, 256>>>(w1, wd1, 9 * 64, 64);
    dup_kernel<<<(64 * 128 + 255) / 256, 256>>>(w2, wd2, 64 * 128, 128);
    dup_kernel<<<(128 * 256 + 255) / 256, 256>>>(w3, wd3, 128 * 256, 256);
    dup_kernel<<<(256 * 384 + 255) / 256, 256>>>(w4, wd4, 256 * 384, 384);

    pack_kernel<<<(B_ * N_ + 255) / 256, 256>>>(pts);
    fps_kernel<<<B_ * 4, 1024, FPS_SMEM>>>(centers_out);
    knn_kernel<<<B_ * M_, 256, KNN_SMEM>>>();
    encoder_kernel<<<B_ * M_ / 2, 256, ENC_SMEM>>>(
        pts, b1, g1, be1, m1, v1, b2, g2, be2, m2, v2,
        b3, g3, be3, m3, v3, b4, tokens);
    pos_kernel<<<B_ * M_, 128>>>(pw1, pb1, pw2, pb2, tokens);
}